// round 1
// baseline (speedup 1.0000x reference)
#include <cuda_runtime.h>

#define B_  256
#define L_  8192
#define E_  64
#define THR_ 1.5f
#define SEG_ 128
#define NSEG_ (L_ / SEG_)          // 64
#define NTH_ 512
#define NWARP_ (NTH_ / 32)         // 16
#define PT_ (L_ / NTH_)            // 16 positions per thread

__global__ __launch_bounds__(NTH_)
void entropy_patcher_kernel(const int* __restrict__ x,
                            const float* __restrict__ w1,
                            const float* __restrict__ b1,
                            const float* __restrict__ w2,
                            const float* __restrict__ b2,
                            float* __restrict__ out)
{
    __shared__ unsigned char  sm_x[L_];           // tokens as bytes
    __shared__ unsigned char  sm_ps[L_];          // patch size per position (3 or 12)
    __shared__ unsigned short sm_cs[L_ + 2];      // prefix sums (exact, max 32768)
    __shared__ float          sm_tab[50];         // entropy term table [t-5][c]
    __shared__ unsigned char  sm_exit[NSEG_ * 12];
    __shared__ unsigned char  sm_entry[NSEG_];
    __shared__ float          sm_hsum[NWARP_][E_];
    __shared__ int            sm_cnt[NWARP_];
    __shared__ int            sm_scan[NWARP_];
    __shared__ float          sm_hsall[E_];
    __shared__ int            sm_n;

    const int row  = blockIdx.x;
    const int tid  = threadIdx.x;
    const int lane = tid & 31;
    const int wid  = tid >> 5;

    const int* xrow   = x + (size_t)row * L_;
    float*     out_blt = out + (size_t)row * E_;
    float*     out_ent = out + (size_t)B_ * E_ + (size_t)row * L_;

    // ---- entropy term table: T[(t-5)*10 + c] = (c/t)*log2(c/t + 1e-12) ----
    if (tid < 50) {
        int c = tid % 10, t = tid / 10 + 5;
        float p = (float)c / (float)t;
        sm_tab[tid] = p * log2f(p + 1e-12f);
    }

    // ---- load x row into smem as bytes (vectorized) ----
    {
        const int4* xv = (const int4*)xrow;
        #pragma unroll
        for (int v = tid; v < L_ / 4; v += NTH_) {
            int4 a = xv[v];
            sm_x[v * 4 + 0] = (unsigned char)a.x;
            sm_x[v * 4 + 1] = (unsigned char)a.y;
            sm_x[v * 4 + 2] = (unsigned char)a.z;
            sm_x[v * 4 + 3] = (unsigned char)a.w;
        }
    }
    __syncthreads();

    // ---- prefix sums (u16, exact) ----
    const int base = tid * PT_;
    int lsum = 0;
    {
        #pragma unroll
        for (int k = 0; k < PT_; k++) lsum += sm_x[base + k];
        int v = lsum;
        #pragma unroll
        for (int d = 1; d < 32; d <<= 1) {
            int u = __shfl_up_sync(0xffffffffu, v, d);
            if (lane >= d) v += u;
        }
        if (lane == 31) sm_scan[wid] = v;
        __syncthreads();
        int woff = 0;
        for (int w = 0; w < wid; w++) woff += sm_scan[w];
        int r = woff + v - lsum;          // exclusive prefix
        if (tid == 0) sm_cs[0] = 0;
        #pragma unroll
        for (int k = 0; k < PT_; k++) {
            r += sm_x[base + k];
            sm_cs[base + k + 1] = (unsigned short)r;
        }
    }

    // ---- entropy (sliding window, packed 4-bit counts) + psize decision ----
    {
        unsigned int cnt = 0;
        int t = 0;
        int lo = base - 4; if (lo < 0) lo = 0;
        int hi = base + 4; if (hi > L_ - 1) hi = L_ - 1;
        for (int q = lo; q <= hi; q++) { cnt += 1u << (4 * sm_x[q]); t++; }
        #pragma unroll 4
        for (int k = 0; k < PT_; k++) {
            int i = base + k;
            const float* tab = &sm_tab[(t - 5) * 10];
            float s = tab[cnt & 15];
            s += tab[(cnt >> 4)  & 15];
            s += tab[(cnt >> 8)  & 15];
            s += tab[(cnt >> 12) & 15];
            s += tab[(cnt >> 16) & 15];
            float ent = -s;
            out_ent[i] = ent;
            sm_ps[i] = (ent > THR_) ? (unsigned char)3 : (unsigned char)12;
            int rm = i - 4;
            if (rm >= 0) { cnt -= 1u << (4 * sm_x[rm]); t--; }
            int ad = i + 5;
            if (ad < L_) { cnt += 1u << (4 * sm_x[ad]); t++; }
        }
    }
    __syncthreads();

    // ---- phase 4: per-(segment, entry-offset) exit offsets, fully parallel ----
    for (int task = tid; task < NSEG_ * 12; task += NTH_) {
        int s = task / 12, e = task % 12;
        int pos = s * SEG_ + e;
        int end = (s + 1) * SEG_;
        while (pos < end) pos += sm_ps[pos];
        sm_exit[task] = (unsigned char)(pos - end);
    }
    __syncthreads();

    // ---- phase 5: sequential composition (64 links) ----
    if (tid == 0) {
        int e = 0;
        for (int s = 0; s < NSEG_; s++) {
            sm_entry[s] = (unsigned char)e;
            e = sm_exit[s * 12 + e];
        }
    }
    __syncthreads();

    // ---- phase 6: parallel segment walks with relu-accumulate ----
    {
        float w1a = w1[lane],      w1b = w1[lane + 32];
        float b1a = b1[lane],      b1b = b1[lane + 32];
        float h0 = 0.f, h1 = 0.f;
        int cnt = 0;
        for (int seg = wid; seg < NSEG_; seg += NWARP_) {
            int pos = seg * SEG_ + sm_entry[seg];
            int end = (seg + 1) * SEG_;
            while (pos < end) {
                int psz = sm_ps[pos];
                int j = pos + psz;
                if (j > L_) j = L_;
                int len = j - pos;
                int sum = (int)sm_cs[j] - (int)sm_cs[pos];
                float m = (float)sum / (float)len;
                h0 += fmaxf(m * w1a + b1a, 0.f);
                h1 += fmaxf(m * w1b + b1b, 0.f);
                cnt++;
                pos = j;
            }
        }
        sm_hsum[wid][lane]      = h0;
        sm_hsum[wid][lane + 32] = h1;
        if (lane == 0) sm_cnt[wid] = cnt;
    }
    __syncthreads();

    // ---- reduce hsum across warps (fixed order => deterministic) ----
    if (tid < E_) {
        float hs = 0.f;
        #pragma unroll
        for (int w = 0; w < NWARP_; w++) hs += sm_hsum[w][tid];
        sm_hsall[tid] = hs;
    }
    if (tid == NTH_ - 1) {
        int n = 0;
        #pragma unroll
        for (int w = 0; w < NWARP_; w++) n += sm_cnt[w];
        sm_n = n;
    }
    __syncthreads();

    // ---- final 64x64 matvec: blt[c] = dot(w2[c,:], hsum)/n + b2[c] ----
    if (tid < E_) {
        const float* w2r = w2 + tid * E_;
        float acc = 0.f;
        #pragma unroll 8
        for (int j = 0; j < E_; j++) acc += sm_hsall[j] * __ldg(&w2r[j]);
        out_blt[tid] = acc / (float)sm_n + b2[tid];
    }
}

extern "C" void kernel_launch(void* const* d_in, const int* in_sizes, int n_in,
                              void* d_out, int out_size)
{
    const int*   x  = (const int*)d_in[0];
    const float* w1 = (const float*)d_in[1];
    const float* b1 = (const float*)d_in[2];
    const float* w2 = (const float*)d_in[3];
    const float* b2 = (const float*)d_in[4];
    entropy_patcher_kernel<<<B_, NTH_>>>(x, w1, b1, w2, b2, (float*)d_out);
}

// round 2
// speedup vs baseline: 1.2608x; 1.2608x over previous
#include <cuda_runtime.h>
#include <math.h>

#define B_    256
#define L_    8192
#define E_    64
#define THR_  1.5f
#define SEG_  128
#define NSEG_ 64               // L_/SEG_
#define NTH_  512
#define NWARP_ 16
#define PT_   16               // positions per thread

struct Smem {
    unsigned int   xw[L_ / 4];        // packed tokens, 1 byte each   (8192 B)
    float          g3[4096];          // entropy: sum of 3 low nibbles (16384 B)
    float          g2[256];           // entropy: sum of 2 high nibbles (1024 B)
    float          f1[16];            // per-count term, t=9
    float          tab[64];           // general table (t-5)*10 + c
    float          ent[L_];           // swizzled entropy staging     (32768 B)
    float          hsum[NWARP_][E_];
    float          hsall[E_];
    unsigned short cs[L_ + 4];        // prefix sums (exact)
    unsigned char  ps[L_];            // patch size per position
    unsigned char  exitt[NSEG_ * 12];
    unsigned char  entry[NSEG_];
    int            cnt[NWARP_];
    int            scanb[NWARP_];
    int            n;
};

// extract token byte at window-relative position r from 7-word register window
#define XB(r) ((w[(r) >> 2] >> (((r) & 3) * 8)) & 15u)
// bank-conflict-reducing swizzle for the entropy staging buffer
#define ESW(i) ((i) ^ (((i) >> 4) & 15))

__global__ __launch_bounds__(NTH_)
void ep_kernel(const int* __restrict__ x,
               const float* __restrict__ w1,
               const float* __restrict__ b1,
               const float* __restrict__ w2,
               const float* __restrict__ b2,
               float* __restrict__ out)
{
    extern __shared__ char dsm[];
    Smem* s = (Smem*)dsm;

    const int row  = blockIdx.x;
    const int tid  = threadIdx.x;
    const int lane = tid & 31;
    const int wid  = tid >> 5;

    const int* xrow    = x + (size_t)row * L_;
    float*     out_blt = out + (size_t)row * E_;
    float*     out_ent = out + (size_t)B_ * E_ + (size_t)row * L_;

    // ---- phase A: load row, pack tokens to bytes; seed f1 table ----
    {
        const int4* xv = (const int4*)xrow;
        #pragma unroll
        for (int v = tid; v < L_ / 4; v += NTH_) {
            int4 a = xv[v];
            s->xw[v] = (unsigned)a.x | ((unsigned)a.y << 8) |
                       ((unsigned)a.z << 16) | ((unsigned)a.w << 24);
        }
    }
    if (tid < 16) {
        float p = (float)tid / 9.0f;
        s->f1[tid] = p * log2f(p + 1e-12f);
    }
    if (tid >= 16 && tid < 16 + 50) {
        int q = tid - 16;
        int c = q % 10, t = q / 10 + 5;
        float p = (float)c / (float)t;
        s->tab[q] = p * log2f(p + 1e-12f);
    }
    __syncthreads();

    // ---- phase B: build fused tables; load register window; local prefix ----
    #pragma unroll
    for (int i = tid; i < 4096; i += NTH_)
        s->g3[i] = s->f1[i & 15] + s->f1[(i >> 4) & 15] + s->f1[(i >> 8) & 15];
    if (tid < 256)
        s->g2[tid] = s->f1[tid & 15] + s->f1[(tid >> 4) & 15];

    const int base = tid * PT_;
    unsigned int w[7];
    {
        int w0 = (base >> 2) - 1;     // word index of (base-4)
        #pragma unroll
        for (int q = 0; q < 7; q++) {
            int wi = w0 + q;
            if (wi < 0) wi = 0;
            if (wi > L_ / 4 - 1) wi = L_ / 4 - 1;
            w[q] = s->xw[wi];
        }
    }
    int lsum = 0;
    {
        #pragma unroll
        for (int k = 0; k < PT_; k++) lsum += (int)XB(k + 4);
        int v = lsum;
        #pragma unroll
        for (int d = 1; d < 32; d <<= 1) {
            int u = __shfl_up_sync(0xffffffffu, v, d);
            if (lane >= d) v += u;
        }
        if (lane == 31) s->scanb[wid] = v;
        __syncthreads();
        int woff = 0;
        for (int ww = 0; ww < wid; ww++) woff += s->scanb[ww];
        int r = woff + v - lsum;      // exclusive prefix at base

        // ---- phase C: entropy + ps + cs, all from registers ----
        unsigned int cnt = 0;
        #pragma unroll
        for (int q = 0; q < 9; q++) cnt += 1u << (XB(q) << 2);

        unsigned int cslo = 0, psw = 0;
        unsigned int* csW = (unsigned int*)s->cs;
        unsigned int* psW = (unsigned int*)s->ps;
        #pragma unroll
        for (int k = 0; k < PT_; k++) {
            int i = base + k;
            // prefix sums, packed pair stores
            if ((k & 1) == 0) cslo = (unsigned)r & 0xFFFFu;
            else              csW[8 * tid + (k >> 1)] = cslo | ((unsigned)r << 16);
            r += (int)XB(k + 4);
            // entropy from fused tables (2 LDS)
            float entv = -(s->g3[cnt & 0xFFFu] + s->g2[(cnt >> 12) & 0xFFu]);
            s->ent[ESW(i)] = entv;
            unsigned int psz = (entv > THR_) ? 3u : 12u;
            psw |= psz << ((k & 3) * 8);
            if ((k & 3) == 3) { psW[4 * tid + (k >> 2)] = psw; psw = 0; }
            // slide window
            cnt -= 1u << (XB(k) << 2);
            cnt += 1u << (XB(k + 9) << 2);
        }
        if (tid == NTH_ - 1) s->cs[L_] = (unsigned short)r;
    }
    __syncthreads();

    // ---- boundary fixup (8 positions with t < 9) ----
    if (tid < 8) {
        int i  = (tid < 4) ? tid : (L_ - 8 + tid);
        int lo = i - 4; if (lo < 0) lo = 0;
        int hi = i + 4; if (hi > L_ - 1) hi = L_ - 1;
        unsigned int c = 0;
        for (int q = lo; q <= hi; q++)
            c += 1u << (((s->xw[q >> 2] >> ((q & 3) * 8)) & 15u) << 2);
        int t = hi - lo + 1;
        const float* tb = &s->tab[(t - 5) * 10];
        float e = -(tb[c & 15] + tb[(c >> 4) & 15] + tb[(c >> 8) & 15] +
                    tb[(c >> 12) & 15] + tb[(c >> 16) & 15]);
        s->ent[ESW(i)] = e;
        s->ps[i] = (e > THR_) ? (unsigned char)3 : (unsigned char)12;
    }
    __syncthreads();

    // ---- phase 4: per-(segment, entry) exit offsets, 2-way ILP per thread ----
    {
        int t1 = tid;
        int s1 = t1 / 12, e1 = t1 % 12;
        int p1 = s1 * SEG_ + e1, q1 = s1 * SEG_ + SEG_;
        bool has2 = (tid < NSEG_ * 12 - NTH_);   // 256 threads get a 2nd task
        int t2 = tid + NTH_;
        int s2 = t2 / 12, e2 = t2 % 12;
        int p2 = has2 ? s2 * SEG_ + e2 : 0;
        int q2 = has2 ? s2 * SEG_ + SEG_ : 0;
        while (p1 < q1 || p2 < q2) {
            if (p1 < q1) p1 += s->ps[p1];
            if (p2 < q2) p2 += s->ps[p2];
        }
        s->exitt[t1] = (unsigned char)(p1 - q1);
        if (has2) s->exitt[t2] = (unsigned char)(p2 - q2);
    }
    __syncthreads();

    // ---- phase 5 (thread 0): compose 64 links  ||  all: copy entropy out ----
    if (tid == 0) {
        int e = 0;
        #pragma unroll 1
        for (int sg = 0; sg < NSEG_; sg++) {
            s->entry[sg] = (unsigned char)e;
            e = s->exitt[sg * 12 + e];
        }
    }
    {
        #pragma unroll
        for (int it = 0; it < 4; it++) {
            int i0 = (tid + it * NTH_) * 4;
            float4 v;
            v.x = s->ent[ESW(i0 + 0)];
            v.y = s->ent[ESW(i0 + 1)];
            v.z = s->ent[ESW(i0 + 2)];
            v.w = s->ent[ESW(i0 + 3)];
            *(float4*)(out_ent + i0) = v;
        }
    }
    __syncthreads();

    // ---- phase 6: warps walk 4 segments concurrently (ILP) ----
    {
        float w1a = w1[lane], w1b = w1[lane + 32];
        float b1a = b1[lane], b1b = b1[lane + 32];
        float h0 = 0.f, h1 = 0.f;
        int   pc = 0;
        int p[4], q[4];
        #pragma unroll
        for (int a = 0; a < 4; a++) {
            int sg = wid + NWARP_ * a;
            p[a] = sg * SEG_ + s->entry[sg];
            q[a] = sg * SEG_ + SEG_;
        }
        while (p[0] < q[0] || p[1] < q[1] || p[2] < q[2] || p[3] < q[3]) {
            #pragma unroll
            for (int a = 0; a < 4; a++) {
                if (p[a] < q[a]) {
                    int psz = s->ps[p[a]];
                    int j = p[a] + psz;
                    if (j > L_) j = L_;
                    int len = j - p[a];
                    int sum = (int)s->cs[j] - (int)s->cs[p[a]];
                    float m = __fdividef((float)sum, (float)len);
                    h0 += fmaxf(fmaf(m, w1a, b1a), 0.f);
                    h1 += fmaxf(fmaf(m, w1b, b1b), 0.f);
                    pc++;
                    p[a] = j;
                }
            }
        }
        s->hsum[wid][lane]      = h0;
        s->hsum[wid][lane + 32] = h1;
        if (lane == 0) s->cnt[wid] = pc;
    }
    __syncthreads();

    // ---- reductions (fixed order) + final 64x64 matvec ----
    if (tid < E_) {
        float hs = 0.f;
        #pragma unroll
        for (int ww = 0; ww < NWARP_; ww++) hs += s->hsum[ww][tid];
        s->hsall[tid] = hs;
    }
    if (tid == NTH_ - 1) {
        int nn = 0;
        #pragma unroll
        for (int ww = 0; ww < NWARP_; ww++) nn += s->cnt[ww];
        s->n = nn;
    }
    __syncthreads();

    if (tid < E_) {
        const float* w2r = w2 + tid * E_;
        float acc = 0.f;
        #pragma unroll 8
        for (int j = 0; j < E_; j++) acc += s->hsall[j] * __ldg(&w2r[j]);
        out_blt[tid] = acc / (float)s->n + b2[tid];
    }
}

extern "C" void kernel_launch(void* const* d_in, const int* in_sizes, int n_in,
                              void* d_out, int out_size)
{
    const int*   x  = (const int*)d_in[0];
    const float* w1 = (const float*)d_in[1];
    const float* b1 = (const float*)d_in[2];
    const float* w2 = (const float*)d_in[3];
    const float* b2 = (const float*)d_in[4];
    cudaFuncSetAttribute(ep_kernel, cudaFuncAttributeMaxDynamicSharedMemorySize,
                         (int)sizeof(Smem));
    ep_kernel<<<B_, NTH_, sizeof(Smem)>>>(x, w1, b1, w2, b2, (float*)d_out);
}

// round 3
// speedup vs baseline: 1.9796x; 1.5702x over previous
#include <cuda_runtime.h>
#include <math.h>

#define B_    256
#define L_    8192
#define E_    64
#define THR_  1.5f
#define SEG_  128
#define NSEG_ 64
#define NTH_  512
#define NWARP_ 16
#define PT_   16

struct Smem {
    unsigned int   xw[L_ / 4];        // packed tokens (1B each)
    float          g3[4096];          // NEGATED sum of 3 low-nibble terms
    float          g2[256];           // NEGATED sum of 2 high-nibble terms
    float          f1[16];            // NEGATED per-count term, t=9
    float          tab[64];           // NEGATED general table (t-5)*10+c
    float          ent[L_];           // swizzled entropy staging
    float          m_tab[62];         // bin -> mean value
    float          hsall[E_];
    float          extra_m;           // truncated last patch mean
    int            extra_c;
    int            hist[62];
    int            scanb[NWARP_];
    unsigned short cs[L_ + 4];        // exact prefix sums
    unsigned char  ps[L_];            // patch size (3 or 12)
    unsigned char  exitt[NSEG_ * 12];
    unsigned char  gmap[8 * 12];      // group-of-8 composed maps
    unsigned char  gentry[8];
};

#define XB(r)  ((w[(r) >> 2] >> (((r) & 3) * 8)) & 15u)
#define ESW(i) ((i) ^ (((i) >> 4) & 15))

__global__ __launch_bounds__(NTH_)
void ep_kernel(const int* __restrict__ x,
               const float* __restrict__ w1,
               const float* __restrict__ b1,
               const float* __restrict__ w2,
               const float* __restrict__ b2,
               float* __restrict__ out)
{
    extern __shared__ char dsm[];
    Smem* s = (Smem*)dsm;

    const int row  = blockIdx.x;
    const int tid  = threadIdx.x;
    const int lane = tid & 31;
    const int wid  = tid >> 5;

    const int* xrow    = x + (size_t)row * L_;
    float*     out_blt = out + (size_t)row * E_;
    float*     out_ent = out + (size_t)B_ * E_ + (size_t)row * L_;

    // ---- phase A: load row (packed), seed tables, zero hist ----
    {
        const int4* xv = (const int4*)xrow;
        #pragma unroll
        for (int v = tid; v < L_ / 4; v += NTH_) {
            int4 a = xv[v];
            s->xw[v] = (unsigned)a.x | ((unsigned)a.y << 8) |
                       ((unsigned)a.z << 16) | ((unsigned)a.w << 24);
        }
    }
    if (tid < 16) {
        float p = (float)tid / 9.0f;
        s->f1[tid] = -(p * log2f(p + 1e-12f));          // negated
    } else if (tid < 16 + 50) {
        int q = tid - 16;
        int c = q % 10, t = q / 10 + 5;
        float p = (float)c / (float)t;
        s->tab[q] = -(p * log2f(p + 1e-12f));           // negated
    } else if (tid < 66 + 62) {
        s->hist[tid - 66] = 0;
    } else if (tid == 128) {
        s->extra_c = 0;
    }
    __syncthreads();

    // ---- phase B: fused tables + register window + block scan ----
    #pragma unroll
    for (int i = tid; i < 4096; i += NTH_)
        s->g3[i] = s->f1[i & 15] + s->f1[(i >> 4) & 15] + s->f1[(i >> 8) & 15];
    if (tid < 256)
        s->g2[tid] = s->f1[tid & 15] + s->f1[(tid >> 4) & 15];

    const int base = tid * PT_;
    unsigned int w[7];
    {
        int w0 = (base >> 2) - 1;
        #pragma unroll
        for (int q = 0; q < 7; q++) {
            int wi = w0 + q;
            if (wi < 0) wi = 0;
            if (wi > L_ / 4 - 1) wi = L_ / 4 - 1;
            w[q] = s->xw[wi];
        }
    }
    int lsum = 0;
    {
        #pragma unroll
        for (int k = 0; k < PT_; k++) lsum += (int)XB(k + 4);
        int v = lsum;
        #pragma unroll
        for (int d = 1; d < 32; d <<= 1) {
            int u = __shfl_up_sync(0xffffffffu, v, d);
            if (lane >= d) v += u;
        }
        if (lane == 31) s->scanb[wid] = v;
        __syncthreads();
        int woff = 0;
        for (int ww = 0; ww < wid; ww++) woff += s->scanb[ww];
        int r = woff + v - lsum;                         // exclusive prefix

        // ---- phase C: entropy + ps + cs ----
        unsigned int cnt = 0;
        #pragma unroll
        for (int q = 0; q < 9; q++) cnt += 1u << (XB(q) << 2);

        const unsigned int txor = (unsigned)(tid & 15);
        unsigned int cslo = 0, psw = 0;
        unsigned int* csW = (unsigned int*)s->cs;
        unsigned int* psW = (unsigned int*)s->ps;
        #pragma unroll
        for (int k = 0; k < PT_; k++) {
            if ((k & 1) == 0) cslo = (unsigned)r & 0xFFFFu;
            else              csW[8 * tid + (k >> 1)] = cslo | ((unsigned)r << 16);
            r += (int)XB(k + 4);
            float entv = s->g3[cnt & 0xFFFu] + s->g2[(cnt >> 12) & 0xFFu];
            s->ent[base + ((unsigned)k ^ txor)] = entv;
            unsigned int psz = (entv > THR_) ? 3u : 12u;
            psw |= psz << ((k & 3) * 8);
            if ((k & 3) == 3) { psW[4 * tid + (k >> 2)] = psw; psw = 0; }
            cnt -= 1u << (XB(k) << 2);
            cnt += 1u << (XB(k + 9) << 2);
        }
        if (tid == NTH_ - 1) s->cs[L_] = (unsigned short)r;
    }
    __syncthreads();

    // ---- boundary fixup (8 edge positions, t<9) ----
    if (tid < 8) {
        int i  = (tid < 4) ? tid : (L_ - 8 + tid);
        int lo = i - 4; if (lo < 0) lo = 0;
        int hi = i + 4; if (hi > L_ - 1) hi = L_ - 1;
        unsigned int c = 0;
        for (int q = lo; q <= hi; q++)
            c += 1u << (((s->xw[q >> 2] >> ((q & 3) * 8)) & 15u) << 2);
        int t = hi - lo + 1;
        const float* tb = &s->tab[(t - 5) * 10];
        float e = tb[c & 15] + tb[(c >> 4) & 15] + tb[(c >> 8) & 15] +
                  tb[(c >> 12) & 15] + tb[(c >> 16) & 15];
        s->ent[ESW(i)] = e;
        s->ps[i] = (e > THR_) ? (unsigned char)3 : (unsigned char)12;
    }
    __syncthreads();

    // ---- phase 4: (segment, entry) exit offsets, 2-way ILP byte walk ----
    {
        int s1 = tid / 12, e1 = tid % 12;
        int p1 = s1 * SEG_ + e1, q1 = s1 * SEG_ + SEG_;
        bool has2 = (tid < NSEG_ * 12 - NTH_);
        int t2 = tid + NTH_;
        int s2 = t2 / 12, e2 = t2 % 12;
        int p2 = has2 ? s2 * SEG_ + e2 : 0;
        int q2 = has2 ? s2 * SEG_ + SEG_ : 0;
        while (p1 < q1 || p2 < q2) {
            if (p1 < q1) p1 += s->ps[p1];
            if (p2 < q2) p2 += s->ps[p2];
        }
        s->exitt[tid] = (unsigned char)(p1 - q1);
        if (has2) s->exitt[t2] = (unsigned char)(p2 - q2);
    }
    __syncthreads();

    // ---- phase 5a: compose 8-segment group maps (96 threads) ----
    if (tid < 96) {
        int g = tid / 12, e = tid % 12;
        int c = e;
        #pragma unroll
        for (int i = 0; i < 8; i++) c = s->exitt[(g * 8 + i) * 12 + c];
        s->gmap[g * 12 + e] = (unsigned char)c;
    }
    __syncthreads();

    // ---- phase 5b (thread 0): 8-link serial compose ----
    if (tid == 0) {
        int e = 0;
        #pragma unroll
        for (int g = 0; g < 8; g++) {
            s->gentry[g] = (unsigned char)e;
            e = s->gmap[g * 12 + e];
        }
    }
    // ---- m_tab build (62 threads) ----
    if (tid >= 64 && tid < 126) {
        int b = tid - 64;
        s->m_tab[b] = (b < 13) ? ((float)b / 3.0f) : ((float)(b - 13) / 12.0f);
    }
    // ---- entropy copy-out (all threads, coalesced) ----
    {
        #pragma unroll
        for (int it = 0; it < 4; it++) {
            int i0 = (tid + it * NTH_) * 4;
            unsigned int tx = (unsigned)((i0 >> 4) & 15);
            float4 v;
            v.x = s->ent[(unsigned)i0 ^ tx];
            v.y = s->ent[(unsigned)(i0 + 1) ^ tx];
            v.z = s->ent[(unsigned)(i0 + 2) ^ tx];
            v.w = s->ent[(unsigned)(i0 + 3) ^ tx];
            *(float4*)(out_ent + i0) = v;
        }
    }
    __syncthreads();

    // ---- phase 6: 64 walkers -> histogram ----
    if (tid < NSEG_) {
        int g = tid >> 3;
        int c = s->gentry[g];
        for (int i = g * 8; i < tid; i++) c = s->exitt[i * 12 + c];
        int pos = tid * SEG_ + c;
        int end = tid * SEG_ + SEG_;
        int csprev = s->cs[pos];
        while (pos < end) {
            int psz = s->ps[pos];
            int j = pos + psz;
            if (j > L_) {                       // truncated final patch
                int sum = (int)s->cs[L_] - csprev;
                s->extra_m = (float)sum / (float)(L_ - pos);
                s->extra_c = 1;
                break;
            }
            int csj = s->cs[j];
            int bin = (psz == 3) ? (csj - csprev) : (13 + csj - csprev);
            atomicAdd(&s->hist[bin], 1);
            csprev = csj;
            pos = j;
        }
    }
    __syncthreads();

    // ---- expand histogram -> hsall ----
    int n = 0;
    float hch = 0.f;
    if (tid < E_) {
        float w1c = w1[tid], b1c = b1[tid];
        #pragma unroll
        for (int b = 0; b < 62; b++) {
            int c = s->hist[b];
            float term = fmaxf(fmaf(s->m_tab[b], w1c, b1c), 0.f);
            hch += (float)c * term;
            n += c;
        }
        if (s->extra_c) {
            hch += fmaxf(fmaf(s->extra_m, w1c, b1c), 0.f);
            n += 1;
        }
        s->hsall[tid] = hch;
    }
    __syncthreads();

    // ---- final 64x64 matvec ----
    if (tid < E_) {
        const float* w2r = w2 + tid * E_;
        float acc = 0.f;
        #pragma unroll 8
        for (int j = 0; j < E_; j++) acc += s->hsall[j] * __ldg(&w2r[j]);
        out_blt[tid] = acc / (float)n + b2[tid];
    }
}

extern "C" void kernel_launch(void* const* d_in, const int* in_sizes, int n_in,
                              void* d_out, int out_size)
{
    const int*   x  = (const int*)d_in[0];
    const float* w1 = (const float*)d_in[1];
    const float* b1 = (const float*)d_in[2];
    const float* w2 = (const float*)d_in[3];
    const float* b2 = (const float*)d_in[4];
    cudaFuncSetAttribute(ep_kernel, cudaFuncAttributeMaxDynamicSharedMemorySize,
                         (int)sizeof(Smem));
    ep_kernel<<<B_, NTH_, sizeof(Smem)>>>(x, w1, b1, w2, b2, (float*)d_out);
}

// round 7
// speedup vs baseline: 2.0104x; 1.0155x over previous
#include <cuda_runtime.h>
#include <math.h>

#define B_    256
#define L_    8192
#define E_    64
#define THR_  1.5f
#define SEG_  128
#define NSEG_ 64
#define NTH_  512
#define NWARP_ 16
#define PT_   16

struct Smem {
    unsigned int   xw[L_ / 4];        // packed tokens (1B each)
    float          ent[L_];           // swizzled entropy staging
    float          m_tab[62];         // bin -> mean value
    float          hsall[E_];
    float          extra_m;           // truncated last patch mean
    int            extra_c;
    int            hist[62];
    int            scanb[NWARP_];
    unsigned short cs[L_ + 4];        // exact prefix sums
    unsigned char  ps[L_];            // patch size (3 or 12)
    unsigned char  exitt[NSEG_ * 12];
    unsigned char  gmap[8 * 12];      // group-of-8 composed maps
    unsigned char  gentry[8];
    float          tab[64];           // exact edge table (negated)
};

#define XB(r)  ((w[(r) >> 2] >> (((r) & 3) * 8)) & 15u)
#define ESW(i) ((i) ^ (((i) >> 4) & 15))

__global__ __launch_bounds__(NTH_)
void ep_kernel(const int* __restrict__ x,
               const float* __restrict__ w1,
               const float* __restrict__ b1,
               const float* __restrict__ w2,
               const float* __restrict__ b2,
               float* __restrict__ out)
{
    extern __shared__ char dsm[];
    Smem* s = (Smem*)dsm;

    const int row  = blockIdx.x;
    const int tid  = threadIdx.x;
    const int lane = tid & 31;
    const int wid  = tid >> 5;

    const int* xrow    = x + (size_t)row * L_;
    float*     out_blt = out + (size_t)row * E_;
    float*     out_ent = out + (size_t)B_ * E_ + (size_t)row * L_;

    // ---- phase A: load row (packed), seed tables, zero hist ----
    {
        const int4* xv = (const int4*)xrow;
        #pragma unroll
        for (int v = tid; v < L_ / 4; v += NTH_) {
            int4 a = xv[v];
            s->xw[v] = (unsigned)a.x | ((unsigned)a.y << 8) |
                       ((unsigned)a.z << 16) | ((unsigned)a.w << 24);
        }
    }
    if (tid < 50) {                                  // exact edge table (negated)
        int c = tid % 10, t = tid / 10 + 5;
        float p = (float)c / (float)t;
        s->tab[tid] = -(p * log2f(p + 1e-12f));
    } else if (tid >= 64 && tid < 64 + 62) {
        s->hist[tid - 64] = 0;
    } else if (tid == 126) {
        s->extra_c = 0;
    }

    // per-lane entropy table in registers (lane index = class count 0..9)
    float f1v, dDec, dInc;
    {
        float p = (float)lane / 9.0f;
        f1v = -(p * log2f(p + 1e-12f));               // negated term (>=0)
        float up = __shfl_up_sync(0xffffffffu, f1v, 1);
        float dn = __shfl_down_sync(0xffffffffu, f1v, 1);
        dDec = up - f1v;      // count c -> c-1 (queried with c>=1)
        dInc = dn - f1v;      // count c -> c+1 (queried with c<=8)
    }
    __syncthreads();

    // ---- phase B: register window + block scan ----
    const int base = tid * PT_;
    unsigned int w[7];
    {
        int w0 = (base >> 2) - 1;
        #pragma unroll
        for (int q = 0; q < 7; q++) {
            int wi = w0 + q;
            if (wi < 0) wi = 0;
            if (wi > L_ / 4 - 1) wi = L_ / 4 - 1;
            w[q] = s->xw[wi];
        }
    }
    int lsum = 0;
    {
        #pragma unroll
        for (int k = 0; k < PT_; k++) lsum += (int)XB(k + 4);
        int v = lsum;
        #pragma unroll
        for (int d = 1; d < 32; d <<= 1) {
            int u = __shfl_up_sync(0xffffffffu, v, d);
            if (lane >= d) v += u;
        }
        if (lane == 31) s->scanb[wid] = v;
        __syncthreads();
        int woff = 0;
        for (int ww = 0; ww < wid; ww++) woff += s->scanb[ww];
        int r = woff + v - lsum;                     // exclusive prefix

        // ---- phase C: entropy via register-shuffle deltas; ps; cs ----
        unsigned int cnt = 0;
        #pragma unroll
        for (int q = 0; q < 9; q++) cnt += 1u << (XB(q) << 2);

        float S = 0.f;
        #pragma unroll
        for (int c = 0; c < 5; c++) {
            int cc = (cnt >> (4 * c)) & 15;
            S += __shfl_sync(0xffffffffu, f1v, cc);
        }

        const unsigned int txor = (unsigned)(tid & 15);
        unsigned int cslo = 0, psw = 0;
        unsigned int* csW = (unsigned int*)s->cs;
        unsigned int* psW = (unsigned int*)s->ps;
        #pragma unroll
        for (int k = 0; k < PT_; k++) {
            if ((k & 1) == 0) cslo = (unsigned)r & 0xFFFFu;
            else              csW[8 * tid + (k >> 1)] = cslo | ((unsigned)r << 16);
            r += (int)XB(k + 4);
            s->ent[base + ((unsigned)k ^ txor)] = S;
            unsigned int psz = (S > THR_) ? 3u : 12u;
            psw |= psz << ((k & 3) * 8);
            if ((k & 3) == 3) { psW[4 * tid + (k >> 2)] = psw; psw = 0; }
            // slide: remove XB(k), add XB(k+9)  (S tracks cnt exactly)
            int a = (int)XB(k);
            int ca = (cnt >> (4 * a)) & 15;
            S += __shfl_sync(0xffffffffu, dDec, ca);
            cnt -= 1u << (4 * a);
            int bcl = (int)XB(k + 9);
            int cb = (cnt >> (4 * bcl)) & 15;
            S += __shfl_sync(0xffffffffu, dInc, cb);
            cnt += 1u << (4 * bcl);
        }
        if (tid == NTH_ - 1) s->cs[L_] = (unsigned short)r;
    }
    __syncthreads();

    // ---- boundary fixup (8 edge positions, t<9), exact table ----
    if (tid < 8) {
        int i  = (tid < 4) ? tid : (L_ - 8 + tid);
        int lo = i - 4; if (lo < 0) lo = 0;
        int hi = i + 4; if (hi > L_ - 1) hi = L_ - 1;
        unsigned int c = 0;
        for (int q = lo; q <= hi; q++)
            c += 1u << (((s->xw[q >> 2] >> ((q & 3) * 8)) & 15u) << 2);
        int t = hi - lo + 1;
        const float* tb = &s->tab[(t - 5) * 10];
        float e = tb[c & 15] + tb[(c >> 4) & 15] + tb[(c >> 8) & 15] +
                  tb[(c >> 12) & 15] + tb[(c >> 16) & 15];
        s->ent[ESW(i)] = e;
        s->ps[i] = (e > THR_) ? (unsigned char)3 : (unsigned char)12;
    }
    __syncthreads();

    // ---- phase 4: (segment, entry) exit offsets, 2-way ILP byte walk ----
    {
        int s1 = tid / 12, e1 = tid % 12;
        int p1 = s1 * SEG_ + e1, q1 = s1 * SEG_ + SEG_;
        bool has2 = (tid < NSEG_ * 12 - NTH_);
        int t2 = tid + NTH_;
        int s2 = t2 / 12, e2 = t2 % 12;
        int p2 = has2 ? s2 * SEG_ + e2 : 0;
        int q2 = has2 ? s2 * SEG_ + SEG_ : 0;
        while (p1 < q1 || p2 < q2) {
            if (p1 < q1) p1 += s->ps[p1];
            if (p2 < q2) p2 += s->ps[p2];
        }
        s->exitt[tid] = (unsigned char)(p1 - q1);
        if (has2) s->exitt[t2] = (unsigned char)(p2 - q2);
    }
    __syncthreads();

    // ---- phase 5a: compose 8-segment group maps (96 threads) ----
    if (tid < 96) {
        int g = tid / 12, e = tid % 12;
        int c = e;
        #pragma unroll
        for (int i = 0; i < 8; i++) c = s->exitt[(g * 8 + i) * 12 + c];
        s->gmap[g * 12 + e] = (unsigned char)c;
    }
    __syncthreads();

    // ---- phase 5b (thread 0): 8-link serial compose ----
    if (tid == 0) {
        int e = 0;
        #pragma unroll
        for (int g = 0; g < 8; g++) {
            s->gentry[g] = (unsigned char)e;
            e = s->gmap[g * 12 + e];
        }
    }
    // ---- m_tab build (62 threads) ----
    if (tid >= 64 && tid < 126) {
        int b = tid - 64;
        s->m_tab[b] = (b < 13) ? ((float)b / 3.0f) : ((float)(b - 13) / 12.0f);
    }
    // ---- entropy copy-out (all threads, coalesced) ----
    {
        #pragma unroll
        for (int it = 0; it < 4; it++) {
            int i0 = (tid + it * NTH_) * 4;
            unsigned int tx = (unsigned)((i0 >> 4) & 15);
            float4 v;
            v.x = s->ent[(unsigned)i0 ^ tx];
            v.y = s->ent[(unsigned)(i0 + 1) ^ tx];
            v.z = s->ent[(unsigned)(i0 + 2) ^ tx];
            v.w = s->ent[(unsigned)(i0 + 3) ^ tx];
            *(float4*)(out_ent + i0) = v;
        }
    }
    __syncthreads();

    // ---- phase 6: 64 walkers -> histogram ----
    if (tid < NSEG_) {
        int g = tid >> 3;
        int c = s->gentry[g];
        for (int i = g * 8; i < tid; i++) c = s->exitt[i * 12 + c];
        int pos = tid * SEG_ + c;
        int end = tid * SEG_ + SEG_;
        int csprev = s->cs[pos];
        while (pos < end) {
            int psz = s->ps[pos];
            int j = pos + psz;
            if (j > L_) {                       // truncated final patch
                int sum = (int)s->cs[L_] - csprev;
                s->extra_m = (float)sum / (float)(L_ - pos);
                s->extra_c = 1;
                break;
            }
            int csj = s->cs[j];
            int bin = (psz == 3) ? (csj - csprev) : (13 + csj - csprev);
            atomicAdd(&s->hist[bin], 1);
            csprev = csj;
            pos = j;
        }
    }
    __syncthreads();

    // ---- expand histogram -> hsall ----
    int n = 0;
    float hch = 0.f;
    if (tid < E_) {
        float w1c = w1[tid], b1c = b1[tid];
        #pragma unroll
        for (int b = 0; b < 62; b++) {
            int c = s->hist[b];
            float term = fmaxf(fmaf(s->m_tab[b], w1c, b1c), 0.f);
            hch += (float)c * term;
            n += c;
        }
        if (s->extra_c) {
            hch += fmaxf(fmaf(s->extra_m, w1c, b1c), 0.f);
            n += 1;
        }
        s->hsall[tid] = hch;
    }
    __syncthreads();

    // ---- final 64x64 matvec ----
    if (tid < E_) {
        const float* w2r = w2 + tid * E_;
        float acc = 0.f;
        #pragma unroll 8
        for (int j = 0; j < E_; j++) acc += s->hsall[j] * __ldg(&w2r[j]);
        out_blt[tid] = acc / (float)n + b2[tid];
    }
}

extern "C" void kernel_launch(void* const* d_in, const int* in_sizes, int n_in,
                              void* d_out, int out_size)
{
    const int*   x  = (const int*)d_in[0];
    const float* w1 = (const float*)d_in[1];
    const float* b1 = (const float*)d_in[2];
    const float* w2 = (const float*)d_in[3];
    const float* b2 = (const float*)d_in[4];
    cudaFuncSetAttribute(ep_kernel, cudaFuncAttributeMaxDynamicSharedMemorySize,
                         (int)sizeof(Smem));
    ep_kernel<<<B_, NTH_, sizeof(Smem)>>>(x, w1, b1, w2, b2, (float*)d_out);
}